// round 15
// baseline (speedup 1.0000x reference)
#include <cuda_runtime.h>

#define IN_F   4096
#define OUT_F  11008
#define TOKENS 8

#define THREADS 512
#define WARPS_PER_BLOCK 16
#define GRID 148

#define NPAIR (OUT_F / 2)                 // 5504 row pairs
#define KCHUNK 2048                       // columns per K-half
#define CHUNK_F4 (KCHUNK / 4)             // 512 float4
#define MAX_LOCAL_PAIRS 38                // ceil(5504/148)
#define MAX_LOCAL_UNITS (2 * MAX_LOCAL_PAIRS)   // 76

__global__ __launch_bounds__(THREADS, 1)
void dql_fused(const float* __restrict__ x,
               const float* __restrict__ W,
               const int*   __restrict__ Q,
               const float* __restrict__ scales,
               const float* __restrict__ zp,
               const float* __restrict__ bias,
               float*       __restrict__ out) {
    // Small static smem only: leaves ~223 KB L1D carveout -> x (128 KB) stays L1-resident
    __shared__ float sumx[TOKENS];
    __shared__ float scratch[MAX_LOCAL_UNITS * 16];
    __shared__ int   ticket;

    if (threadIdx.x == 0) ticket = 0;
    __syncthreads();   // ticket visible

    const int warp  = threadIdx.x >> 5;
    const int lane  = threadIdx.x & 31;

    // ---- sumx: warp t reduces token t from global (L2-resident, tiny) ----
    // (visibility to consumers ordered by the final __syncthreads)
    if (warp < TOKENS) {
        float s = 0.f;
        #pragma unroll 4
        for (int i = lane; i < IN_F; i += 32) s += __ldg(&x[warp * IN_F + i]);
        #pragma unroll
        for (int off = 16; off; off >>= 1) s += __shfl_xor_sync(0xffffffffu, s, off);
        if (lane == 0) sumx[warp] = s;
    }

    // ---- contiguous per-block pair range ----
    const int pair_start = (int)(((long long)blockIdx.x * NPAIR) / GRID);
    const int pair_end   = (int)(((long long)(blockIdx.x + 1) * NPAIR) / GRID);
    const int n_units    = 2 * (pair_end - pair_start);   // 74 or 76

    const float4* x4 = (const float4*)x;   // x read directly; L1 caches it

    // ---- free-running compute: warps dynamically grab units ----
    for (;;) {
        int ul0 = 0;
        if (lane == 0) ul0 = atomicAdd(&ticket, 1);
        const int ul = __shfl_sync(0xffffffffu, ul0, 0);
        if (ul >= n_units) break;

        const int pair  = pair_start + (ul >> 1);
        const int khalf = ul & 1;
        const int o0 = pair << 1;
        const int o1 = o0 + 1;
        const float s0 = scales[o0];
        const float s1 = scales[o1];

        const float4* w0 = (const float4*)(W + (size_t)o0 * IN_F + khalf * KCHUNK);
        const float4* w1 = (const float4*)(W + (size_t)o1 * IN_F + khalf * KCHUNK);
        const int4*   q0 = (const int4*)(Q + (size_t)o0 * IN_F + khalf * KCHUNK);
        const int4*   q1 = (const int4*)(Q + (size_t)o1 * IN_F + khalf * KCHUNK);
        const float4* xb = x4 + khalf * CHUNK_F4;   // token stride = IN_F/4

        float acc0[TOKENS], acc1[TOKENS];
        #pragma unroll
        for (int t = 0; t < TOKENS; t++) { acc0[t] = 0.f; acc1[t] = 0.f; }

        // 512 float4 per K-half / 32 lanes = 16 iterations; unroll 4
        // W/Q: streaming loads (evict-first, keep x in L1); x: __ldg (L1 hit after warm)
        #pragma unroll 4
        for (int it = 0; it < CHUNK_F4 / 32; ++it) {
            const int c = it * 32 + lane;
            float4 wa = __ldcs(&w0[c]);
            float4 wb = __ldcs(&w1[c]);
            int4   qa = __ldcs(&q0[c]);
            int4   qb = __ldcs(&q1[c]);

            float4 fa, fb;
            fa.x = fmaf(s0, (float)qa.x, wa.x);
            fa.y = fmaf(s0, (float)qa.y, wa.y);
            fa.z = fmaf(s0, (float)qa.z, wa.z);
            fa.w = fmaf(s0, (float)qa.w, wa.w);
            fb.x = fmaf(s1, (float)qb.x, wb.x);
            fb.y = fmaf(s1, (float)qb.y, wb.y);
            fb.z = fmaf(s1, (float)qb.z, wb.z);
            fb.w = fmaf(s1, (float)qb.w, wb.w);

            #pragma unroll
            for (int t = 0; t < TOKENS; t++) {
                float4 xv = __ldg(&xb[t * (IN_F / 4) + c]);
                acc0[t] = fmaf(fa.x, xv.x, acc0[t]);
                acc0[t] = fmaf(fa.y, xv.y, acc0[t]);
                acc0[t] = fmaf(fa.z, xv.z, acc0[t]);
                acc0[t] = fmaf(fa.w, xv.w, acc0[t]);
                acc1[t] = fmaf(fb.x, xv.x, acc1[t]);
                acc1[t] = fmaf(fb.y, xv.y, acc1[t]);
                acc1[t] = fmaf(fb.z, xv.z, acc1[t]);
                acc1[t] = fmaf(fb.w, xv.w, acc1[t]);
            }
        }

        // Segmented fold: 16 values summed across 32 lanes in 31 shfls.
        float v16[16];
        #pragma unroll
        for (int t = 0; t < TOKENS; t++) { v16[2*t] = acc0[t]; v16[2*t+1] = acc1[t]; }
        #pragma unroll
        for (int i = 0; i < 16; i++) v16[i] += __shfl_xor_sync(0xffffffffu, v16[i], 16);
        float v8[8];
        #pragma unroll
        for (int i = 0; i < 8; i++) v8[i] = (lane & 16) ? v16[2*i+1] : v16[2*i];
        #pragma unroll
        for (int i = 0; i < 8; i++) v8[i] += __shfl_xor_sync(0xffffffffu, v8[i], 8);
        float v4[4];
        #pragma unroll
        for (int i = 0; i < 4; i++) v4[i] = (lane & 8) ? v8[2*i+1] : v8[2*i];
        #pragma unroll
        for (int i = 0; i < 4; i++) v4[i] += __shfl_xor_sync(0xffffffffu, v4[i], 4);
        float v2[2];
        #pragma unroll
        for (int i = 0; i < 2; i++) v2[i] = (lane & 4) ? v4[2*i+1] : v4[2*i];
        #pragma unroll
        for (int i = 0; i < 2; i++) v2[i] += __shfl_xor_sync(0xffffffffu, v2[i], 2);
        float v1 = (lane & 2) ? v2[1] : v2[0];
        v1 += __shfl_xor_sync(0xffffffffu, v1, 1);

        // deposit 16 partials; unique scratch row per local unit
        if (!(lane & 1)) {
            scratch[ul * 16 + (lane >> 1)] = v1;
        }
    }

    __syncthreads();   // the ONLY combine barrier: all deposits + sumx visible

    // ---- consume: all 16 warps split the block's pairs ----
    {
        const int npl = pair_end - pair_start;
        const int rr = (lane >> 4) & 1;
        const int t  = ((lane >> 3) & 1) | (((lane >> 2) & 1) << 1) | (((lane >> 1) & 1) << 2);
        const float sx = sumx[t];
        if (!(lane & 1)) {
            for (int pl = warp; pl < npl; pl += WARPS_PER_BLOCK) {
                const int o = ((pair_start + pl) << 1) + rr;
                float total = scratch[(2 * pl) * 16 + (lane >> 1)]
                            + scratch[(2 * pl + 1) * 16 + (lane >> 1)];
                out[t * OUT_F + o] = total + fmaf(-scales[o] * zp[o], sx, bias[o]);
            }
        }
    }
}

extern "C" void kernel_launch(void* const* d_in, const int* in_sizes, int n_in,
                              void* d_out, int out_size) {
    const float* x      = (const float*)d_in[0];
    const float* W      = (const float*)d_in[1];
    const int*   Q      = (const int*)d_in[2];
    const float* scales = (const float*)d_in[3];
    const float* zp     = (const float*)d_in[4];
    const float* bias   = (const float*)d_in[5];
    float* out = (float*)d_out;

    dql_fused<<<GRID, THREADS>>>(x, W, Q, scales, zp, bias, out);
}

// round 16
// speedup vs baseline: 1.1770x; 1.1770x over previous
#include <cuda_runtime.h>

#define IN_F   4096
#define OUT_F  11008
#define TOKENS 8

#define THREADS 512
#define WARPS_PER_BLOCK 16
#define GRID 148

#define NPAIR (OUT_F / 2)                 // 5504 row pairs
#define KCHUNK 2048                       // columns per K-half
#define CHUNK_F4 (KCHUNK / 4)             // 512 float4
#define MAX_LOCAL_PAIRS 38                // ceil(5504/148)
#define MAX_LOCAL_UNITS (2 * MAX_LOCAL_PAIRS)   // 76

// smem: x[8][4096] | sumx[8] | scratch[76][16] | ticket
#define SMEM_FLOATS (TOKENS * IN_F + TOKENS + MAX_LOCAL_UNITS * 16 + 4)
#define SMEM_BYTES  (SMEM_FLOATS * 4)

__device__ __forceinline__ void l2_prefetch(const void* p) {
    asm volatile("prefetch.global.L2 [%0];" :: "l"(p));
}

__global__ __launch_bounds__(THREADS, 1)
void dql_fused(const float* __restrict__ x,
               const float* __restrict__ W,
               const int*   __restrict__ Q,
               const float* __restrict__ scales,
               const float* __restrict__ zp,
               const float* __restrict__ bias,
               float*       __restrict__ out) {
    extern __shared__ float xs[];                 // [TOKENS][IN_F]
    float* sumx    = xs + TOKENS * IN_F;          // [8]
    float* scratch = sumx + TOKENS;               // [76][16]
    int*   ticket  = (int*)(scratch + MAX_LOCAL_UNITS * 16);

    const int warp  = threadIdx.x >> 5;
    const int lane  = threadIdx.x & 31;

    // ---- contiguous per-block pair range ----
    const int pair_start = (int)(((long long)blockIdx.x * NPAIR) / GRID);
    const int pair_end   = (int)(((long long)(blockIdx.x + 1) * NPAIR) / GRID);
    const int n_units    = 2 * (pair_end - pair_start);   // 74 or 76

    // ---- L2 prefetch of this warp's predicted first unit (overlaps staging) ----
    // Unit 'warp' (ticket order ≈ warp order at launch). Hint only; no correctness impact.
    if (warp < n_units) {
        const int pair  = pair_start + (warp >> 1);
        const int khalf = warp & 1;
        const int o0 = pair << 1;
        const float* wb0 = W + (size_t)o0 * IN_F + khalf * KCHUNK;
        const float* wb1 = W + (size_t)(o0 + 1) * IN_F + khalf * KCHUNK;
        const int*   qb0 = Q + (size_t)o0 * IN_F + khalf * KCHUNK;
        const int*   qb1 = Q + (size_t)(o0 + 1) * IN_F + khalf * KCHUNK;
        #pragma unroll
        for (int it = 0; it < 8; ++it) {
            const int c = (it * 32 + lane) * 4;   // float4 granularity
            l2_prefetch(wb0 + c);
            l2_prefetch(wb1 + c);
            l2_prefetch(qb0 + c);
            l2_prefetch(qb1 + c);
        }
    }

    // ---- stage x into shared (128 KB), vectorized; init ticket ----
    if (threadIdx.x == 0) *ticket = 0;
    {
        const float4* x4 = (const float4*)x;
        float4* xs4w = (float4*)xs;
        #pragma unroll
        for (int i = threadIdx.x; i < TOKENS * IN_F / 4; i += THREADS)
            xs4w[i] = x4[i];
    }
    __syncthreads();   // x + ticket visible

    // ---- in-kernel sumx: warp t reduces token t from shared ----
    // (visibility to consumers ordered by the final __syncthreads)
    if (warp < TOKENS) {
        float s = 0.f;
        #pragma unroll 4
        for (int i = lane; i < IN_F; i += 32) s += xs[warp * IN_F + i];
        #pragma unroll
        for (int off = 16; off; off >>= 1) s += __shfl_xor_sync(0xffffffffu, s, off);
        if (lane == 0) sumx[warp] = s;
    }

    const float4* xs4 = (const float4*)xs;

    // ---- free-running compute: warps dynamically grab units ----
    for (;;) {
        int ul0 = 0;
        if (lane == 0) ul0 = atomicAdd(ticket, 1);
        const int ul = __shfl_sync(0xffffffffu, ul0, 0);
        if (ul >= n_units) break;

        const int pair  = pair_start + (ul >> 1);
        const int khalf = ul & 1;
        const int o0 = pair << 1;
        const int o1 = o0 + 1;
        const float s0 = scales[o0];
        const float s1 = scales[o1];

        const float4* w0 = (const float4*)(W + (size_t)o0 * IN_F + khalf * KCHUNK);
        const float4* w1 = (const float4*)(W + (size_t)o1 * IN_F + khalf * KCHUNK);
        const int4*   q0 = (const int4*)(Q + (size_t)o0 * IN_F + khalf * KCHUNK);
        const int4*   q1 = (const int4*)(Q + (size_t)o1 * IN_F + khalf * KCHUNK);
        const float4* xb = xs4 + khalf * CHUNK_F4;

        float acc0[TOKENS], acc1[TOKENS];
        #pragma unroll
        for (int t = 0; t < TOKENS; t++) { acc0[t] = 0.f; acc1[t] = 0.f; }

        // 512 float4 per K-half / 32 lanes = 16 iterations; unroll 4
        // W/Q streamed evict-first (.cs): keep L2 ways for x / reduce thrash
        #pragma unroll 4
        for (int it = 0; it < CHUNK_F4 / 32; ++it) {
            const int c = it * 32 + lane;
            float4 wa = __ldcs(&w0[c]);
            float4 wb = __ldcs(&w1[c]);
            int4   qa = __ldcs(&q0[c]);
            int4   qb = __ldcs(&q1[c]);

            float4 fa, fb;
            fa.x = fmaf(s0, (float)qa.x, wa.x);
            fa.y = fmaf(s0, (float)qa.y, wa.y);
            fa.z = fmaf(s0, (float)qa.z, wa.z);
            fa.w = fmaf(s0, (float)qa.w, wa.w);
            fb.x = fmaf(s1, (float)qb.x, wb.x);
            fb.y = fmaf(s1, (float)qb.y, wb.y);
            fb.z = fmaf(s1, (float)qb.z, wb.z);
            fb.w = fmaf(s1, (float)qb.w, wb.w);

            #pragma unroll
            for (int t = 0; t < TOKENS; t++) {
                float4 xv = xb[t * (IN_F / 4) + c];
                acc0[t] = fmaf(fa.x, xv.x, acc0[t]);
                acc0[t] = fmaf(fa.y, xv.y, acc0[t]);
                acc0[t] = fmaf(fa.z, xv.z, acc0[t]);
                acc0[t] = fmaf(fa.w, xv.w, acc0[t]);
                acc1[t] = fmaf(fb.x, xv.x, acc1[t]);
                acc1[t] = fmaf(fb.y, xv.y, acc1[t]);
                acc1[t] = fmaf(fb.z, xv.z, acc1[t]);
                acc1[t] = fmaf(fb.w, xv.w, acc1[t]);
            }
        }

        // Segmented fold: 16 values summed across 32 lanes in 31 shfls.
        float v16[16];
        #pragma unroll
        for (int t = 0; t < TOKENS; t++) { v16[2*t] = acc0[t]; v16[2*t+1] = acc1[t]; }
        #pragma unroll
        for (int i = 0; i < 16; i++) v16[i] += __shfl_xor_sync(0xffffffffu, v16[i], 16);
        float v8[8];
        #pragma unroll
        for (int i = 0; i < 8; i++) v8[i] = (lane & 16) ? v16[2*i+1] : v16[2*i];
        #pragma unroll
        for (int i = 0; i < 8; i++) v8[i] += __shfl_xor_sync(0xffffffffu, v8[i], 8);
        float v4[4];
        #pragma unroll
        for (int i = 0; i < 4; i++) v4[i] = (lane & 8) ? v8[2*i+1] : v8[2*i];
        #pragma unroll
        for (int i = 0; i < 4; i++) v4[i] += __shfl_xor_sync(0xffffffffu, v4[i], 4);
        float v2[2];
        #pragma unroll
        for (int i = 0; i < 2; i++) v2[i] = (lane & 4) ? v4[2*i+1] : v4[2*i];
        #pragma unroll
        for (int i = 0; i < 2; i++) v2[i] += __shfl_xor_sync(0xffffffffu, v2[i], 2);
        float v1 = (lane & 2) ? v2[1] : v2[0];
        v1 += __shfl_xor_sync(0xffffffffu, v1, 1);

        // deposit 16 partials; unique scratch row per local unit
        if (!(lane & 1)) {
            scratch[ul * 16 + (lane >> 1)] = v1;
        }
    }

    __syncthreads();   // the ONLY combine barrier: all deposits + sumx visible

    // ---- consume: all 16 warps split the block's pairs ----
    {
        const int npl = pair_end - pair_start;
        const int rr = (lane >> 4) & 1;
        const int t  = ((lane >> 3) & 1) | (((lane >> 2) & 1) << 1) | (((lane >> 1) & 1) << 2);
        const float sx = sumx[t];
        if (!(lane & 1)) {
            for (int pl = warp; pl < npl; pl += WARPS_PER_BLOCK) {
                const int o = ((pair_start + pl) << 1) + rr;
                float total = scratch[(2 * pl) * 16 + (lane >> 1)]
                            + scratch[(2 * pl + 1) * 16 + (lane >> 1)];
                out[t * OUT_F + o] = total + fmaf(-scales[o] * zp[o], sx, bias[o]);
            }
        }
    }
}

extern "C" void kernel_launch(void* const* d_in, const int* in_sizes, int n_in,
                              void* d_out, int out_size) {
    const float* x      = (const float*)d_in[0];
    const float* W      = (const float*)d_in[1];
    const int*   Q      = (const int*)d_in[2];
    const float* scales = (const float*)d_in[3];
    const float* zp     = (const float*)d_in[4];
    const float* bias   = (const float*)d_in[5];
    float* out = (float*)d_out;

    cudaFuncSetAttribute(dql_fused, cudaFuncAttributeMaxDynamicSharedMemorySize,
                         SMEM_BYTES);

    dql_fused<<<GRID, THREADS, SMEM_BYTES>>>(x, W, Q, scales, zp, bias, out);
}